// round 11
// baseline (speedup 1.0000x reference)
#include <cuda_runtime.h>
#include <cuda_bf16.h>
#include <math.h>
#include <stdint.h>

// Problem constants
#define B_ 64
#define T_ 512
#define D_ 512
#define H_ 1024
#define G_ 4096           // 4*H
#define KS_ 4             // k-split for recurrence
#define KB_ 256           // k per recurrence block (H_/KS_)
#define NBLK 128          // persistent grid (1 block/SM, all resident)

// Device-global scratch (allocation-free per harness rules)
__device__ float g_xw[(size_t)B_ * T_ * G_];     // x @ W_ih^T + bias  [b*T+t][4H]
__device__ __nv_bfloat16 g_hmh[B_ * H_];         // h*hid_mask bf16 hi [b][j]
__device__ __nv_bfloat16 g_hml[B_ * H_];         // h*hid_mask bf16 lo [b][j]
__device__ float g_part[KS_][G_][B_];            // split-k partials [ks][rowc][b]
__device__ unsigned int g_bar;

// ---------------------------- helpers --------------------------------------
__device__ __forceinline__ uint32_t smem_u32(const void* p) {
    uint32_t a;
    asm("{ .reg .u64 t; cvta.to.shared.u64 t, %1; cvt.u32.u64 %0, t; }"
        : "=r"(a) : "l"(p));
    return a;
}
// Split-2 bf16: v = hi + lo (lo itself bf16-rounded); packs pairs (a,b)
__device__ __forceinline__ void split2(float a, float b, uint32_t& hi, uint32_t& lo) {
    __nv_bfloat16 ah = __float2bfloat16(a);
    __nv_bfloat16 bh = __float2bfloat16(b);
    float la = a - __bfloat162float(ah);
    float lb = b - __bfloat162float(bh);
    __nv_bfloat162 h2 = __floats2bfloat162_rn(a, b);
    __nv_bfloat162 l2 = __floats2bfloat162_rn(la, lb);
    hi = *(uint32_t*)&h2;
    lo = *(uint32_t*)&l2;
}
__device__ __forceinline__ void ldm4(uint32_t addr, uint32_t r[4]) {
    asm volatile("ldmatrix.sync.aligned.m8n8.x4.shared.b16 {%0,%1,%2,%3}, [%4];"
        : "=r"(r[0]), "=r"(r[1]), "=r"(r[2]), "=r"(r[3]) : "r"(addr));
}
__device__ __forceinline__ void mma16816(float c[4], const uint32_t a[4],
                                         const uint32_t b[2]) {
    asm volatile(
        "mma.sync.aligned.m16n8k16.row.col.f32.bf16.bf16.f32 "
        "{%0,%1,%2,%3}, {%4,%5,%6,%7}, {%8,%9}, {%0,%1,%2,%3};"
        : "+f"(c[0]), "+f"(c[1]), "+f"(c[2]), "+f"(c[3])
        : "r"(a[0]), "r"(a[1]), "r"(a[2]), "r"(a[3]), "r"(b[0]), "r"(b[1]));
}
__device__ __forceinline__ void cp16(uint32_t smem_dst, const void* gsrc) {
    asm volatile("cp.async.cg.shared.global [%0], [%1], 16;"
                 :: "r"(smem_dst), "l"(gsrc) : "memory");
}
// Fast, overflow-safe activations (rel err ~2^-22, irrelevant vs 1e-3 budget)
__device__ __forceinline__ float sigf(float x) {
    return 1.f / (1.f + __expf(-x));
}
__device__ __forceinline__ float tanh_fast(float x) {
    float a = fabsf(x);
    float e = __expf(2.f * a);
    float r = 1.f - 2.f / (e + 1.f);
    return copysignf(r, x);
}

// ---------------------------------------------------------------------------
// No-op pad kernels: shift k_persist to launch slot #6 so ncu (-s 5 -c 1)
// finally captures it instead of k_init.
// ---------------------------------------------------------------------------
__global__ void k_nop() {}

// ---------------------------------------------------------------------------
// Init: zero h bf16 state + barrier
// ---------------------------------------------------------------------------
__global__ void k_init() {
    int i = blockIdx.x * blockDim.x + threadIdx.x;
    if (i < B_ * H_ / 2) ((uint32_t*)g_hmh)[i] = 0u;
    else                 ((uint32_t*)g_hml)[i - B_ * H_ / 2] = 0u;
    if (i == 0) g_bar = 0u;
}

// ---------------------------------------------------------------------------
// Input GEMM (HMMA, split-2 bf16):
//   g_xw[m,n] = sum_d x_masked[m,d] * W_ih[n,d] + (b_ih+b_hh)[n]
// Block: 256 thr (8 warps), tile M=128 x N=128, K chunks of 64 (8 chunks).
// Warp tile 64m x 32n = 4x4 m16n8k16 tiles. 3 split passes. Occupancy 2.
// SMEM row stride 72 bf16 (144B): conflict-free ldmatrix.
// ---------------------------------------------------------------------------
#define IG_AH   0
#define IG_AL   18432
#define IG_BH   36864
#define IG_BL   55296
#define IG_BIAS 73728
#define IG_SMEM 74240

__global__ __launch_bounds__(256, 2) void k_igemm(
    const float* __restrict__ x, const float* __restrict__ Wih,
    const float* __restrict__ bih, const float* __restrict__ bhh,
    const float* __restrict__ in_mask)
{
    extern __shared__ __align__(16) char smem[];
    const uint32_t sb = smem_u32(smem);
    const int tid = threadIdx.x;
    const int l   = tid & 31;
    const int w   = tid >> 5;
    const int wy  = w >> 2;         // 0..1 (m half)
    const int wx  = w & 3;          // 0..3 (n quarter)
    const int n0  = blockIdx.x * 128;
    const int m0  = blockIdx.y * 128;

    float* sBias = (float*)(smem + IG_BIAS);
    if (tid < 128) sBias[tid] = bih[n0 + tid] + bhh[n0 + tid];

    // ldmatrix lane-address components
    const int rA = ((l >> 3) & 1) * 8 + (l & 7);
    const int kA = (l >> 4) * 8;
    const int nB = ((l >> 4) & 1) * 8 + (l & 7);
    const int kB = ((l >> 3) & 1) * 8;
    const uint32_t aOff = (uint32_t)(((wy * 64 + rA) * 72 + kA) * 2);
    const uint32_t bOff = (uint32_t)(((wx * 32 + nB) * 72 + kB) * 2);

    float acc[4][4][4] = {};

    for (int ch = 0; ch < 8; ch++) {
        const int kk = ch * 64;
        __syncthreads();
        // Stage x tile: 128 rows x 64 k -> hi/lo
#pragma unroll
        for (int i = 0; i < 8; i++) {
            int v = tid + i * 256;
            int r = v >> 4;
            int kq = (v & 15) * 4;
            int m = m0 + r;
            float4 xv = *(const float4*)(x + (size_t)m * D_ + kk + kq);
            if ((m & (T_ - 1)) == 0) {
                const float* im = in_mask + (m >> 9) * D_ + kk + kq;
                xv.x *= im[0]; xv.y *= im[1]; xv.z *= im[2]; xv.w *= im[3];
            }
            uint32_t h0, l0, h1, l1;
            split2(xv.x, xv.y, h0, l0);
            split2(xv.z, xv.w, h1, l1);
            uint32_t off = (uint32_t)((r * 72 + kq) * 2);
            *(uint2*)(smem + IG_AH + off) = make_uint2(h0, h1);
            *(uint2*)(smem + IG_AL + off) = make_uint2(l0, l1);
        }
        // Stage Wih tile: 128 rows x 64 k -> hi/lo
#pragma unroll
        for (int i = 0; i < 8; i++) {
            int v = tid + i * 256;
            int r = v >> 4;
            int kq = (v & 15) * 4;
            float4 wv = *(const float4*)(Wih + (size_t)(n0 + r) * D_ + kk + kq);
            uint32_t h0, l0, h1, l1;
            split2(wv.x, wv.y, h0, l0);
            split2(wv.z, wv.w, h1, l1);
            uint32_t off = (uint32_t)((r * 72 + kq) * 2);
            *(uint2*)(smem + IG_BH + off) = make_uint2(h0, h1);
            *(uint2*)(smem + IG_BL + off) = make_uint2(l0, l1);
        }
        __syncthreads();

#pragma unroll
        for (int pass = 0; pass < 3; pass++) {
            uint32_t aBase = sb + ((pass == 1) ? IG_AL : IG_AH) + aOff;
            uint32_t bBase = sb + ((pass == 2) ? IG_BL : IG_BH) + bOff;
#pragma unroll
            for (int ks = 0; ks < 4; ks++) {
                uint32_t af[4][4];
#pragma unroll
                for (int mt = 0; mt < 4; mt++)
                    ldm4(aBase + mt * 2304 + ks * 32, af[mt]);
                uint32_t bf[4][2];
#pragma unroll
                for (int p = 0; p < 2; p++) {
                    uint32_t r4[4];
                    ldm4(bBase + p * 2304 + ks * 32, r4);
                    bf[p * 2][0] = r4[0]; bf[p * 2][1] = r4[1];
                    bf[p * 2 + 1][0] = r4[2]; bf[p * 2 + 1][1] = r4[3];
                }
#pragma unroll
                for (int mt = 0; mt < 4; mt++)
#pragma unroll
                    for (int nt = 0; nt < 4; nt++)
                        mma16816(acc[mt][nt], af[mt], bf[nt]);
            }
        }
    }

    // Epilogue: bias + store
#pragma unroll
    for (int mt = 0; mt < 4; mt++) {
        int mrow = m0 + wy * 64 + mt * 16 + (l >> 2);
#pragma unroll
        for (int nt = 0; nt < 4; nt++) {
            int nl = wx * 32 + nt * 8 + (l & 3) * 2;
            float b0 = sBias[nl], b1 = sBias[nl + 1];
            *(float2*)(g_xw + (size_t)mrow * G_ + n0 + nl) =
                make_float2(acc[mt][nt][0] + b0, acc[mt][nt][1] + b1);
            *(float2*)(g_xw + (size_t)(mrow + 8) * G_ + n0 + nl) =
                make_float2(acc[mt][nt][2] + b0, acc[mt][nt][3] + b1);
        }
    }
}

// ---------------------------------------------------------------------------
// Cheap grid barrier (CG grid.sync pattern: block bar + one-thread gpu fence)
// ---------------------------------------------------------------------------
__device__ __forceinline__ void gsync(unsigned int& tgt) {
    __syncthreads();
    if (threadIdx.x == 0) {
        asm volatile("fence.acq_rel.gpu;" ::: "memory");
        atomicAdd(&g_bar, 1u);
        tgt += NBLK;
        while (*(volatile unsigned int*)&g_bar < tgt) {}
        asm volatile("fence.acq_rel.gpu;" ::: "memory");
    }
    __syncthreads();
}

// ---------------------------------------------------------------------------
// Persistent recurrence (HMMA). Grid 128 blocks x 256 threads (8 warps).
// Block (rt = bid>>2, ks = bid&3): A = 128 gathered gate-rows
//   grow(lr) = (lr>>5)*H + rt*32 + (lr&31),  k-slice [ks*256, +256).
// W slice bf16 hi/lo SMEM ONCE (132 KB, resident). h pre-split in global
// (g_hmh/g_hml); staging = cp.async in TWO k-halves, half 1 in flight while
// MMA runs on half 0. xw prefetch hoisted to step top.
// Per step: prefetch xw -> issue cp.async (2 groups) -> MMA half0 -> MMA half1
//   -> store partials -> gsync -> reduce+pointwise -> gsync (skipped at T-1).
// SMEM row stride 264 bf16 (528B): conflict-free ldmatrix.
// ---------------------------------------------------------------------------
#define PSS     264
#define PS_WH   0
#define PS_WL   67584
#define PS_HH   135168
#define PS_HL   168960
#define PS_SMEM 202752

__global__ __launch_bounds__(256, 1) void k_persist(
    const float* __restrict__ Whh,
    const float* __restrict__ hid_mask,
    const float* __restrict__ out_mask,
    float* __restrict__ out)
{
    extern __shared__ __align__(16) char smem[];
    const uint32_t sb = smem_u32(smem);
    const int tid = threadIdx.x;
    const int l   = tid & 31;
    const int w   = tid >> 5;
    const int bid = blockIdx.x;
    const int rt  = bid >> 2;
    const int ks  = bid & 3;
    const int kb  = ks * KB_;

    // ---- Convert + stage W slice once: 128 gathered rows x 256 k ----
#pragma unroll
    for (int i = 0; i < 32; i++) {
        int v  = tid + i * 256;            // 0..8191
        int lr = v >> 6;                   // 0..127
        int kq = (v & 63) * 4;             // 0..252
        int grow = (lr >> 5) * H_ + rt * 32 + (lr & 31);
        float4 wv = *(const float4*)(Whh + (size_t)grow * H_ + kb + kq);
        uint32_t h0, l0, h1, l1;
        split2(wv.x, wv.y, h0, l0);
        split2(wv.z, wv.w, h1, l1);
        uint32_t off = (uint32_t)((lr * PSS + kq) * 2);
        *(uint2*)(smem + PS_WH + off) = make_uint2(h0, h1);
        *(uint2*)(smem + PS_WL + off) = make_uint2(l0, l1);
    }

    // ---- Register-resident state: thread owns (b, j0) and (b, j0+1) ----
    const int bb = tid & 63;               // batch
    const int jp = tid >> 6;               // 0..3 -> j pair
    const int j0 = rt * 32 + ks * 8 + jp * 2;
    const int hidx0 = bb * H_ + j0;
    float c_reg[2] = {0.f, 0.f};
    float2 hmk = *(const float2*)(hid_mask + hidx0);
    float2 omk = *(const float2*)(out_mask + hidx0);

    // ldmatrix lane-address components
    const int rA = ((l >> 3) & 1) * 8 + (l & 7);
    const int kA = (l >> 4) * 8;
    const int nB = ((l >> 4) & 1) * 8 + (l & 7);
    const int kB = ((l >> 3) & 1) * 8;
    const uint32_t aOff = (uint32_t)(((w * 16 + rA) * PSS + kA) * 2);
    const uint32_t bOff = (uint32_t)((nB * PSS + kB) * 2);
    unsigned int tgt = 0;

    for (int t = 0; t < T_; t++) {
        // ---- xw(t) prefetch: independent; hides under staging + MMA ----
        float xwv[2][4];
#pragma unroll
        for (int u = 0; u < 2; u++)
#pragma unroll
            for (int g = 0; g < 4; g++)
                xwv[u][g] = __ldcg(&g_xw[(size_t)(bb * T_ + t) * G_ + g * H_ + j0 + u]);

        // ---- Issue h staging: two k-halves as separate cp.async groups ----
        // (safe without a leading sync: gsync at the end of the previous step
        //  ordered all sH readers before these writes)
#pragma unroll
        for (int half = 0; half < 2; half++) {
#pragma unroll
            for (int i = 0; i < 4; i++) {
                int v  = tid + i * 256;        // 0..1023
                int b  = v >> 4;               // 0..63
                int kq = (v & 15) * 8 + half * 128;
                uint32_t off = (uint32_t)((b * PSS + kq) * 2);
                cp16(sb + PS_HH + off, g_hmh + (size_t)b * H_ + kb + kq);
                cp16(sb + PS_HL + off, g_hml + (size_t)b * H_ + kb + kq);
            }
            asm volatile("cp.async.commit_group;" ::: "memory");
        }

        float acc[8][4];
#pragma unroll
        for (int nt = 0; nt < 8; nt++)
#pragma unroll
            for (int q = 0; q < 4; q++) acc[nt][q] = 0.f;

        // ---- MMA over two k-halves; half 1 staging overlaps half 0 MMA ----
        asm volatile("cp.async.wait_group 1;" ::: "memory");
        __syncthreads();
#pragma unroll
        for (int half = 0; half < 2; half++) {
            if (half == 1) {
                asm volatile("cp.async.wait_group 0;" ::: "memory");
                __syncthreads();
            }
#pragma unroll
            for (int pass = 0; pass < 3; pass++) {
                uint32_t aBase = sb + ((pass == 1) ? PS_WL : PS_WH) + aOff + half * 256;
                uint32_t bBase = sb + ((pass == 2) ? PS_HL : PS_HH) + bOff + half * 256;
#pragma unroll 4
                for (int kk = 0; kk < 8; kk++) {
                    uint32_t af[4];
                    ldm4(aBase + kk * 32, af);
                    uint32_t bf[8][2];
#pragma unroll
                    for (int p = 0; p < 4; p++) {
                        uint32_t r4[4];
                        ldm4(bBase + p * 8448 + kk * 32, r4);
                        bf[p * 2][0] = r4[0]; bf[p * 2][1] = r4[1];
                        bf[p * 2 + 1][0] = r4[2]; bf[p * 2 + 1][1] = r4[3];
                    }
#pragma unroll
                    for (int nt = 0; nt < 8; nt++)
                        mma16816(acc[nt], af, bf[nt]);
                }
            }
        }

        // ---- Store partials: [ks][rowc][b] ----
        {
            int row = rt * 128 + w * 16 + (l >> 2);
#pragma unroll
            for (int nt = 0; nt < 8; nt++) {
                int b = nt * 8 + (l & 3) * 2;
                *(float2*)(&g_part[ks][row][b]) = make_float2(acc[nt][0], acc[nt][1]);
                *(float2*)(&g_part[ks][row + 8][b]) = make_float2(acc[nt][2], acc[nt][3]);
            }
        }

        gsync(tgt);

        // ---- Reduce + pointwise (2 adjacent j per thread) ----
        float cn[2], hn[2], hm[2];
#pragma unroll
        for (int u = 0; u < 2; u++) {
            float s[4];
#pragma unroll
            for (int g = 0; g < 4; g++) {
                int rowc = rt * 128 + g * 32 + ks * 8 + jp * 2 + u;
                float a = xwv[u][g];
                a += __ldcg(&g_part[0][rowc][bb]);
                a += __ldcg(&g_part[1][rowc][bb]);
                a += __ldcg(&g_part[2][rowc][bb]);
                a += __ldcg(&g_part[3][rowc][bb]);
                s[g] = a;
            }
            float i_ = sigf(s[0]);
            float f_ = sigf(s[1]);
            float gg = tanh_fast(s[2]);
            float o_ = sigf(s[3]);
            cn[u] = fmaf(f_, c_reg[u], i_ * gg);
            hn[u] = o_ * tanh_fast(cn[u]);
            hm[u] = hn[u] * ((u == 0) ? hmk.x : hmk.y);
            c_reg[u] = cn[u];
        }
        // Vectorized state + output stores (adjacent j)
        {
            __nv_bfloat16 h0 = __float2bfloat16(hm[0]);
            __nv_bfloat16 h1 = __float2bfloat16(hm[1]);
            __nv_bfloat16 l0 = __float2bfloat16(hm[0] - __bfloat162float(h0));
            __nv_bfloat16 l1 = __float2bfloat16(hm[1] - __bfloat162float(h1));
            *(__nv_bfloat162*)(g_hmh + hidx0) = __nv_bfloat162(h0, h1);
            *(__nv_bfloat162*)(g_hml + hidx0) = __nv_bfloat162(l0, l1);
            *(float2*)(out + (size_t)(bb * T_ + t) * H_ + j0) =
                make_float2(hn[0] * omk.x, hn[1] * omk.y);
            if (t == T_ - 1) {
                *(float2*)(out + (size_t)B_ * T_ * H_ + hidx0) =
                    make_float2(hm[0], hm[1]);                                 // h_f
                *(float2*)(out + (size_t)B_ * T_ * H_ + (size_t)B_ * H_ + hidx0) =
                    make_float2(cn[0], cn[1]);                                 // c_f
            }
        }

        if (t + 1 < T_) gsync(tgt);
    }
}

// ---------------------------------------------------------------------------
// Launch: 6 graph nodes — 3 nops pad the ncu skip window (-s 5 -c 1) so the
// captured launch is k_persist, not k_init.
// ---------------------------------------------------------------------------
extern "C" void kernel_launch(void* const* d_in, const int* in_sizes, int n_in,
                              void* d_out, int out_size)
{
    const float* x        = (const float*)d_in[0];
    const float* Wih      = (const float*)d_in[1];
    const float* Whh      = (const float*)d_in[2];
    const float* bih      = (const float*)d_in[3];
    const float* bhh      = (const float*)d_in[4];
    const float* in_mask  = (const float*)d_in[5];
    const float* hid_mask = (const float*)d_in[6];
    const float* out_mask = (const float*)d_in[7];
    float* out = (float*)d_out;

    static int attr_set = 0;
    if (!attr_set) {
        cudaFuncSetAttribute(k_igemm,   cudaFuncAttributeMaxDynamicSharedMemorySize, IG_SMEM);
        cudaFuncSetAttribute(k_persist, cudaFuncAttributeMaxDynamicSharedMemorySize, PS_SMEM);
        attr_set = 1;
    }

    k_nop<<<1, 32>>>();
    k_nop<<<1, 32>>>();
    k_nop<<<1, 32>>>();
    k_init<<<256, 256>>>();
    k_igemm<<<dim3(G_ / 128, (B_ * T_) / 128), 256, IG_SMEM>>>(x, Wih, bih, bhh, in_mask);
    k_persist<<<NBLK, 256, PS_SMEM>>>(Whh, hid_mask, out_mask, out);
}

// round 12
// speedup vs baseline: 1.1900x; 1.1900x over previous
#include <cuda_runtime.h>
#include <cuda_bf16.h>
#include <math.h>
#include <stdint.h>

// Problem constants
#define B_ 64
#define T_ 512
#define D_ 512
#define H_ 1024
#define G_ 4096           // 4*H
#define KS_ 4             // k-split for recurrence
#define KB_ 256           // k per recurrence block (H_/KS_)
#define NBLK 128          // persistent grid (1 block/SM, all resident)

// Device-global scratch (allocation-free per harness rules)
__device__ float g_xw[(size_t)B_ * T_ * G_];     // x @ W_ih^T + bias  [b*T+t][4H]
__device__ __nv_bfloat16 g_hmh[B_ * H_];         // h*hid_mask bf16 hi [b][j]
__device__ __nv_bfloat16 g_hml[B_ * H_];         // h*hid_mask bf16 lo [b][j]
__device__ float g_part[KS_][G_][B_];            // split-k partials [ks][rowc][b]
__device__ unsigned int g_bar;

// ---------------------------- helpers --------------------------------------
__device__ __forceinline__ uint32_t smem_u32(const void* p) {
    uint32_t a;
    asm("{ .reg .u64 t; cvta.to.shared.u64 t, %1; cvt.u32.u64 %0, t; }"
        : "=r"(a) : "l"(p));
    return a;
}
// Split-2 bf16: v = hi + lo (lo itself bf16-rounded); packs pairs (a,b)
__device__ __forceinline__ void split2(float a, float b, uint32_t& hi, uint32_t& lo) {
    __nv_bfloat16 ah = __float2bfloat16(a);
    __nv_bfloat16 bh = __float2bfloat16(b);
    float la = a - __bfloat162float(ah);
    float lb = b - __bfloat162float(bh);
    __nv_bfloat162 h2 = __floats2bfloat162_rn(a, b);
    __nv_bfloat162 l2 = __floats2bfloat162_rn(la, lb);
    hi = *(uint32_t*)&h2;
    lo = *(uint32_t*)&l2;
}
__device__ __forceinline__ void ldm4(uint32_t addr, uint32_t r[4]) {
    asm volatile("ldmatrix.sync.aligned.m8n8.x4.shared.b16 {%0,%1,%2,%3}, [%4];"
        : "=r"(r[0]), "=r"(r[1]), "=r"(r[2]), "=r"(r[3]) : "r"(addr));
}
__device__ __forceinline__ void mma16816(float c[4], const uint32_t a[4],
                                         const uint32_t b[2]) {
    asm volatile(
        "mma.sync.aligned.m16n8k16.row.col.f32.bf16.bf16.f32 "
        "{%0,%1,%2,%3}, {%4,%5,%6,%7}, {%8,%9}, {%0,%1,%2,%3};"
        : "+f"(c[0]), "+f"(c[1]), "+f"(c[2]), "+f"(c[3])
        : "r"(a[0]), "r"(a[1]), "r"(a[2]), "r"(a[3]), "r"(b[0]), "r"(b[1]));
}
__device__ __forceinline__ void cp16(uint32_t smem_dst, const void* gsrc) {
    asm volatile("cp.async.cg.shared.global [%0], [%1], 16;"
                 :: "r"(smem_dst), "l"(gsrc) : "memory");
}
// Fast, overflow-safe activations (rel err ~2^-22, irrelevant vs 1e-3 budget)
__device__ __forceinline__ float sigf(float x) {
    return 1.f / (1.f + __expf(-x));
}
__device__ __forceinline__ float tanh_fast(float x) {
    float a = fabsf(x);
    float e = __expf(2.f * a);
    float r = 1.f - 2.f / (e + 1.f);
    return copysignf(r, x);
}

// ---------------------------------------------------------------------------
// Init: zero h bf16 state + barrier
// ---------------------------------------------------------------------------
__global__ void k_init() {
    int i = blockIdx.x * blockDim.x + threadIdx.x;
    if (i < B_ * H_ / 2) ((uint32_t*)g_hmh)[i] = 0u;
    else                 ((uint32_t*)g_hml)[i - B_ * H_ / 2] = 0u;
    if (i == 0) g_bar = 0u;
}

// ---------------------------------------------------------------------------
// Input GEMM (HMMA, split-2 bf16):
//   g_xw[m,n] = sum_d x_masked[m,d] * W_ih[n,d] + (b_ih+b_hh)[n]
// Block: 256 thr (8 warps), tile M=128 x N=128, K chunks of 64 (8 chunks).
// Warp tile 64m x 32n = 4x4 m16n8k16 tiles. 3 split passes. Occupancy 2.
// SMEM row stride 72 bf16 (144B): conflict-free ldmatrix.
// ---------------------------------------------------------------------------
#define IG_AH   0
#define IG_AL   18432
#define IG_BH   36864
#define IG_BL   55296
#define IG_BIAS 73728
#define IG_SMEM 74240

__global__ __launch_bounds__(256, 2) void k_igemm(
    const float* __restrict__ x, const float* __restrict__ Wih,
    const float* __restrict__ bih, const float* __restrict__ bhh,
    const float* __restrict__ in_mask)
{
    extern __shared__ __align__(16) char smem[];
    const uint32_t sb = smem_u32(smem);
    const int tid = threadIdx.x;
    const int l   = tid & 31;
    const int w   = tid >> 5;
    const int wy  = w >> 2;         // 0..1 (m half)
    const int wx  = w & 3;          // 0..3 (n quarter)
    const int n0  = blockIdx.x * 128;
    const int m0  = blockIdx.y * 128;

    float* sBias = (float*)(smem + IG_BIAS);
    if (tid < 128) sBias[tid] = bih[n0 + tid] + bhh[n0 + tid];

    // ldmatrix lane-address components
    const int rA = ((l >> 3) & 1) * 8 + (l & 7);
    const int kA = (l >> 4) * 8;
    const int nB = ((l >> 4) & 1) * 8 + (l & 7);
    const int kB = ((l >> 3) & 1) * 8;
    const uint32_t aOff = (uint32_t)(((wy * 64 + rA) * 72 + kA) * 2);
    const uint32_t bOff = (uint32_t)(((wx * 32 + nB) * 72 + kB) * 2);

    float acc[4][4][4] = {};

    for (int ch = 0; ch < 8; ch++) {
        const int kk = ch * 64;
        __syncthreads();
        // Stage x tile: 128 rows x 64 k -> hi/lo
#pragma unroll
        for (int i = 0; i < 8; i++) {
            int v = tid + i * 256;
            int r = v >> 4;
            int kq = (v & 15) * 4;
            int m = m0 + r;
            float4 xv = *(const float4*)(x + (size_t)m * D_ + kk + kq);
            if ((m & (T_ - 1)) == 0) {
                const float* im = in_mask + (m >> 9) * D_ + kk + kq;
                xv.x *= im[0]; xv.y *= im[1]; xv.z *= im[2]; xv.w *= im[3];
            }
            uint32_t h0, l0, h1, l1;
            split2(xv.x, xv.y, h0, l0);
            split2(xv.z, xv.w, h1, l1);
            uint32_t off = (uint32_t)((r * 72 + kq) * 2);
            *(uint2*)(smem + IG_AH + off) = make_uint2(h0, h1);
            *(uint2*)(smem + IG_AL + off) = make_uint2(l0, l1);
        }
        // Stage Wih tile: 128 rows x 64 k -> hi/lo
#pragma unroll
        for (int i = 0; i < 8; i++) {
            int v = tid + i * 256;
            int r = v >> 4;
            int kq = (v & 15) * 4;
            float4 wv = *(const float4*)(Wih + (size_t)(n0 + r) * D_ + kk + kq);
            uint32_t h0, l0, h1, l1;
            split2(wv.x, wv.y, h0, l0);
            split2(wv.z, wv.w, h1, l1);
            uint32_t off = (uint32_t)((r * 72 + kq) * 2);
            *(uint2*)(smem + IG_BH + off) = make_uint2(h0, h1);
            *(uint2*)(smem + IG_BL + off) = make_uint2(l0, l1);
        }
        __syncthreads();

#pragma unroll
        for (int pass = 0; pass < 3; pass++) {
            uint32_t aBase = sb + ((pass == 1) ? IG_AL : IG_AH) + aOff;
            uint32_t bBase = sb + ((pass == 2) ? IG_BL : IG_BH) + bOff;
#pragma unroll
            for (int ks = 0; ks < 4; ks++) {
                uint32_t af[4][4];
#pragma unroll
                for (int mt = 0; mt < 4; mt++)
                    ldm4(aBase + mt * 2304 + ks * 32, af[mt]);
                uint32_t bf[4][2];
#pragma unroll
                for (int p = 0; p < 2; p++) {
                    uint32_t r4[4];
                    ldm4(bBase + p * 2304 + ks * 32, r4);
                    bf[p * 2][0] = r4[0]; bf[p * 2][1] = r4[1];
                    bf[p * 2 + 1][0] = r4[2]; bf[p * 2 + 1][1] = r4[3];
                }
#pragma unroll
                for (int mt = 0; mt < 4; mt++)
#pragma unroll
                    for (int nt = 0; nt < 4; nt++)
                        mma16816(acc[mt][nt], af[mt], bf[nt]);
            }
        }
    }

    // Epilogue: bias + store
#pragma unroll
    for (int mt = 0; mt < 4; mt++) {
        int mrow = m0 + wy * 64 + mt * 16 + (l >> 2);
#pragma unroll
        for (int nt = 0; nt < 4; nt++) {
            int nl = wx * 32 + nt * 8 + (l & 3) * 2;
            float b0 = sBias[nl], b1 = sBias[nl + 1];
            *(float2*)(g_xw + (size_t)mrow * G_ + n0 + nl) =
                make_float2(acc[mt][nt][0] + b0, acc[mt][nt][1] + b1);
            *(float2*)(g_xw + (size_t)(mrow + 8) * G_ + n0 + nl) =
                make_float2(acc[mt][nt][2] + b0, acc[mt][nt][3] + b1);
        }
    }
}

// ---------------------------------------------------------------------------
// Cheap grid barrier (CG grid.sync pattern: block bar + one-thread gpu fence)
// ---------------------------------------------------------------------------
__device__ __forceinline__ void gsync(unsigned int& tgt) {
    __syncthreads();
    if (threadIdx.x == 0) {
        asm volatile("fence.acq_rel.gpu;" ::: "memory");
        atomicAdd(&g_bar, 1u);
        tgt += NBLK;
        while (*(volatile unsigned int*)&g_bar < tgt) {}
        asm volatile("fence.acq_rel.gpu;" ::: "memory");
    }
    __syncthreads();
}

// ---------------------------------------------------------------------------
// Persistent recurrence (HMMA). Grid 128 blocks x 256 threads (8 warps).
// Block (rt = bid>>2, ks = bid&3): A = 128 gathered gate-rows
//   grow(lr) = (lr>>5)*H + rt*32 + (lr&31),  k-slice [ks*256, +256).
// W slice bf16 hi/lo SMEM ONCE (132 KB, resident). h pre-split in global.
// R12 change (only one vs R10): warp tile m16x64 -> m32x32
//   warp w: mq = w&3 (32-row group), nh = w>>2 (32-batch half)
//   per k-step: 2 A ldm + 2 B ldm for 8 MMAs (0.5 ldm/MMA vs 0.625)
// Per step: cp.async h -> warp GEMM (3 passes) -> prefetch xw -> partials
//   -> gsync -> reduce+pointwise -> gsync (skipped at t=T-1).
// SMEM row stride 264 bf16 (528B): conflict-free ldmatrix.
// ---------------------------------------------------------------------------
#define PSS     264
#define PS_WH   0
#define PS_WL   67584
#define PS_HH   135168
#define PS_HL   168960
#define PS_SMEM 202752

__global__ __launch_bounds__(256, 1) void k_persist(
    const float* __restrict__ Whh,
    const float* __restrict__ hid_mask,
    const float* __restrict__ out_mask,
    float* __restrict__ out)
{
    extern __shared__ __align__(16) char smem[];
    const uint32_t sb = smem_u32(smem);
    const int tid = threadIdx.x;
    const int l   = tid & 31;
    const int w   = tid >> 5;
    const int mq  = w & 3;                 // 32-row group within 128
    const int nh  = w >> 2;                // 32-batch half
    const int bid = blockIdx.x;
    const int rt  = bid >> 2;
    const int ks  = bid & 3;
    const int kb  = ks * KB_;

    // ---- Convert + stage W slice once: 128 gathered rows x 256 k ----
#pragma unroll
    for (int i = 0; i < 32; i++) {
        int v  = tid + i * 256;            // 0..8191
        int lr = v >> 6;                   // 0..127
        int kq = (v & 63) * 4;             // 0..252
        int grow = (lr >> 5) * H_ + rt * 32 + (lr & 31);
        float4 wv = *(const float4*)(Whh + (size_t)grow * H_ + kb + kq);
        uint32_t h0, l0, h1, l1;
        split2(wv.x, wv.y, h0, l0);
        split2(wv.z, wv.w, h1, l1);
        uint32_t off = (uint32_t)((lr * PSS + kq) * 2);
        *(uint2*)(smem + PS_WH + off) = make_uint2(h0, h1);
        *(uint2*)(smem + PS_WL + off) = make_uint2(l0, l1);
    }

    // ---- Register-resident state: thread owns (b, j0) and (b, j0+1) ----
    const int bb = tid & 63;               // batch
    const int jp = tid >> 6;               // 0..3 -> j pair
    const int j0 = rt * 32 + ks * 8 + jp * 2;
    const int hidx0 = bb * H_ + j0;
    float c_reg[2] = {0.f, 0.f};
    float2 hmk = *(const float2*)(hid_mask + hidx0);
    float2 omk = *(const float2*)(out_mask + hidx0);

    // ldmatrix lane-address components
    const int rA = ((l >> 3) & 1) * 8 + (l & 7);
    const int kA = (l >> 4) * 8;
    const int nB = ((l >> 4) & 1) * 8 + (l & 7);
    const int kB = ((l >> 3) & 1) * 8;
    const uint32_t aOff = (uint32_t)(((mq * 32 + rA) * PSS + kA) * 2);
    const uint32_t bOff = (uint32_t)(((nh * 32 + nB) * PSS + kB) * 2);
    unsigned int tgt = 0;

    for (int t = 0; t < T_; t++) {
        // ---- Stage h slice via cp.async: 64 b x 256 k (hi + lo) ----
        __syncthreads();
#pragma unroll
        for (int i = 0; i < 8; i++) {
            int v  = tid + i * 256;        // 0..2047
            int b  = v >> 5;               // 0..63
            int kq = (v & 31) * 8;         // 0..248
            uint32_t off = (uint32_t)((b * PSS + kq) * 2);
            cp16(sb + PS_HH + off, g_hmh + (size_t)b * H_ + kb + kq);
            cp16(sb + PS_HL + off, g_hml + (size_t)b * H_ + kb + kq);
        }
        asm volatile("cp.async.wait_all;" ::: "memory");
        __syncthreads();

        // ---- Warp GEMM: 32 rows x 32 batches, K=256, 3 passes ----
        float acc[2][4][4];
#pragma unroll
        for (int mt = 0; mt < 2; mt++)
#pragma unroll
            for (int nt = 0; nt < 4; nt++)
#pragma unroll
                for (int q = 0; q < 4; q++) acc[mt][nt][q] = 0.f;

#pragma unroll
        for (int pass = 0; pass < 3; pass++) {
            uint32_t aBase = sb + ((pass == 1) ? PS_WL : PS_WH) + aOff;
            uint32_t bBase = sb + ((pass == 2) ? PS_HL : PS_HH) + bOff;
#pragma unroll 4
            for (int kk = 0; kk < 16; kk++) {
                uint32_t af[2][4];
                ldm4(aBase + kk * 32, af[0]);
                ldm4(aBase + 8448 + kk * 32, af[1]);   // +16 rows (16*PSS*2)
                uint32_t bf[4][2];
#pragma unroll
                for (int p = 0; p < 2; p++) {
                    uint32_t r4[4];
                    ldm4(bBase + p * 8448 + kk * 32, r4);  // +16 batches per p
                    bf[p * 2][0] = r4[0]; bf[p * 2][1] = r4[1];
                    bf[p * 2 + 1][0] = r4[2]; bf[p * 2 + 1][1] = r4[3];
                }
#pragma unroll
                for (int mt = 0; mt < 2; mt++)
#pragma unroll
                    for (int nt = 0; nt < 4; nt++)
                        mma16816(acc[mt][nt], af[mt], bf[nt]);
            }
        }

        // ---- Prefetch xw(t) (hides DRAM latency under stores+barrier) ----
        float xwv[2][4];
#pragma unroll
        for (int u = 0; u < 2; u++)
#pragma unroll
            for (int g = 0; g < 4; g++)
                xwv[u][g] = g_xw[(size_t)(bb * T_ + t) * G_ + g * H_ + j0 + u];

        // ---- Store partials: [ks][rowc][b] ----
#pragma unroll
        for (int mt = 0; mt < 2; mt++) {
            int row = rt * 128 + mq * 32 + mt * 16 + (l >> 2);
#pragma unroll
            for (int nt = 0; nt < 4; nt++) {
                int b = nh * 32 + nt * 8 + (l & 3) * 2;
                *(float2*)(&g_part[ks][row][b]) =
                    make_float2(acc[mt][nt][0], acc[mt][nt][1]);
                *(float2*)(&g_part[ks][row + 8][b]) =
                    make_float2(acc[mt][nt][2], acc[mt][nt][3]);
            }
        }

        gsync(tgt);

        // ---- Reduce + pointwise (2 adjacent j per thread) ----
        float cn[2], hn[2], hm[2];
#pragma unroll
        for (int u = 0; u < 2; u++) {
            float s[4];
#pragma unroll
            for (int g = 0; g < 4; g++) {
                int rowc = rt * 128 + g * 32 + ks * 8 + jp * 2 + u;
                float a = xwv[u][g];
                a += __ldcg(&g_part[0][rowc][bb]);
                a += __ldcg(&g_part[1][rowc][bb]);
                a += __ldcg(&g_part[2][rowc][bb]);
                a += __ldcg(&g_part[3][rowc][bb]);
                s[g] = a;
            }
            float i_ = sigf(s[0]);
            float f_ = sigf(s[1]);
            float gg = tanh_fast(s[2]);
            float o_ = sigf(s[3]);
            cn[u] = fmaf(f_, c_reg[u], i_ * gg);
            hn[u] = o_ * tanh_fast(cn[u]);
            hm[u] = hn[u] * ((u == 0) ? hmk.x : hmk.y);
            c_reg[u] = cn[u];
        }
        // Vectorized state + output stores (adjacent j)
        {
            __nv_bfloat16 h0 = __float2bfloat16(hm[0]);
            __nv_bfloat16 h1 = __float2bfloat16(hm[1]);
            __nv_bfloat16 l0 = __float2bfloat16(hm[0] - __bfloat162float(h0));
            __nv_bfloat16 l1 = __float2bfloat16(hm[1] - __bfloat162float(h1));
            *(__nv_bfloat162*)(g_hmh + hidx0) = __nv_bfloat162(h0, h1);
            *(__nv_bfloat162*)(g_hml + hidx0) = __nv_bfloat162(l0, l1);
            *(float2*)(out + (size_t)(bb * T_ + t) * H_ + j0) =
                make_float2(hn[0] * omk.x, hn[1] * omk.y);
            if (t == T_ - 1) {
                *(float2*)(out + (size_t)B_ * T_ * H_ + hidx0) =
                    make_float2(hm[0], hm[1]);                                 // h_f
                *(float2*)(out + (size_t)B_ * T_ * H_ + (size_t)B_ * H_ + hidx0) =
                    make_float2(cn[0], cn[1]);                                 // c_f
            }
        }

        if (t + 1 < T_) gsync(tgt);
    }
}

// ---------------------------------------------------------------------------
// Launch: 3 graph nodes (init, input GEMM, persistent recurrence)
// ---------------------------------------------------------------------------
extern "C" void kernel_launch(void* const* d_in, const int* in_sizes, int n_in,
                              void* d_out, int out_size)
{
    const float* x        = (const float*)d_in[0];
    const float* Wih      = (const float*)d_in[1];
    const float* Whh      = (const float*)d_in[2];
    const float* bih      = (const float*)d_in[3];
    const float* bhh      = (const float*)d_in[4];
    const float* in_mask  = (const float*)d_in[5];
    const float* hid_mask = (const float*)d_in[6];
    const float* out_mask = (const float*)d_in[7];
    float* out = (float*)d_out;

    static int attr_set = 0;
    if (!attr_set) {
        cudaFuncSetAttribute(k_igemm,   cudaFuncAttributeMaxDynamicSharedMemorySize, IG_SMEM);
        cudaFuncSetAttribute(k_persist, cudaFuncAttributeMaxDynamicSharedMemorySize, PS_SMEM);
        attr_set = 1;
    }

    k_init<<<256, 256>>>();
    k_igemm<<<dim3(G_ / 128, (B_ * T_) / 128), 256, IG_SMEM>>>(x, Wih, bih, bhh, in_mask);
    k_persist<<<NBLK, 256, PS_SMEM>>>(Whh, hid_mask, out_mask, out);
}

// round 13
// speedup vs baseline: 1.2225x; 1.0273x over previous
#include <cuda_runtime.h>
#include <cuda_bf16.h>
#include <math.h>
#include <stdint.h>

// Problem constants
#define B_ 64
#define T_ 512
#define D_ 512
#define H_ 1024
#define G_ 4096           // 4*H
#define KS_ 4             // k-split for recurrence
#define KB_ 256           // k per recurrence block (H_/KS_)
#define NBLK 128          // persistent grid (1 block/SM, all resident)

// Device-global scratch (allocation-free per harness rules)
__device__ float g_xw[(size_t)B_ * T_ * G_];       // x @ W_ih^T + bias  [b*T+t][4H]
__device__ __nv_bfloat16 g_hmh[2][B_ * H_];        // h*hid_mask bf16 hi, parity buffers
__device__ __nv_bfloat16 g_hml[2][B_ * H_];        // h*hid_mask bf16 lo, parity buffers
__device__ float g_part[KS_][G_][B_];              // split-k partials [ks][rowc][b]
__device__ unsigned int g_bar;                     // global barrier counter
__device__ unsigned int g_bar1[32 * 32];           // per-rt quartet counters (128B apart)

// ---------------------------- helpers --------------------------------------
__device__ __forceinline__ uint32_t smem_u32(const void* p) {
    uint32_t a;
    asm("{ .reg .u64 t; cvta.to.shared.u64 t, %1; cvt.u32.u64 %0, t; }"
        : "=r"(a) : "l"(p));
    return a;
}
// Split-2 bf16: v = hi + lo (lo itself bf16-rounded); packs pairs (a,b)
__device__ __forceinline__ void split2(float a, float b, uint32_t& hi, uint32_t& lo) {
    __nv_bfloat16 ah = __float2bfloat16(a);
    __nv_bfloat16 bh = __float2bfloat16(b);
    float la = a - __bfloat162float(ah);
    float lb = b - __bfloat162float(bh);
    __nv_bfloat162 h2 = __floats2bfloat162_rn(a, b);
    __nv_bfloat162 l2 = __floats2bfloat162_rn(la, lb);
    hi = *(uint32_t*)&h2;
    lo = *(uint32_t*)&l2;
}
__device__ __forceinline__ void ldm4(uint32_t addr, uint32_t r[4]) {
    asm volatile("ldmatrix.sync.aligned.m8n8.x4.shared.b16 {%0,%1,%2,%3}, [%4];"
        : "=r"(r[0]), "=r"(r[1]), "=r"(r[2]), "=r"(r[3]) : "r"(addr));
}
__device__ __forceinline__ void mma16816(float c[4], const uint32_t a[4],
                                         const uint32_t b[2]) {
    asm volatile(
        "mma.sync.aligned.m16n8k16.row.col.f32.bf16.bf16.f32 "
        "{%0,%1,%2,%3}, {%4,%5,%6,%7}, {%8,%9}, {%0,%1,%2,%3};"
        : "+f"(c[0]), "+f"(c[1]), "+f"(c[2]), "+f"(c[3])
        : "r"(a[0]), "r"(a[1]), "r"(a[2]), "r"(a[3]), "r"(b[0]), "r"(b[1]));
}
__device__ __forceinline__ void cp16(uint32_t smem_dst, const void* gsrc) {
    asm volatile("cp.async.cg.shared.global [%0], [%1], 16;"
                 :: "r"(smem_dst), "l"(gsrc) : "memory");
}
// Fast, overflow-safe activations (rel err ~2^-22, irrelevant vs 1e-3 budget)
__device__ __forceinline__ float sigf(float x) {
    return 1.f / (1.f + __expf(-x));
}
__device__ __forceinline__ float tanh_fast(float x) {
    float a = fabsf(x);
    float e = __expf(2.f * a);
    float r = 1.f - 2.f / (e + 1.f);
    return copysignf(r, x);
}

// ---------------------------------------------------------------------------
// Init: zero both h parity buffers + barrier counters
// ---------------------------------------------------------------------------
__global__ void k_init() {
    int i = blockIdx.x * blockDim.x + threadIdx.x;   // 0..65535
    ((uint32_t*)g_hmh)[i] = 0u;                      // 2*64K bf16 = 64K u32
    ((uint32_t*)g_hml)[i] = 0u;
    if (i == 0) g_bar = 0u;
    if (i < 32 * 32) g_bar1[i] = 0u;
}

// ---------------------------------------------------------------------------
// Input GEMM (HMMA, split-2 bf16):
//   g_xw[m,n] = sum_d x_masked[m,d] * W_ih[n,d] + (b_ih+b_hh)[n]
// Block: 256 thr (8 warps), tile M=128 x N=128, K chunks of 64 (8 chunks).
// Warp tile 64m x 32n = 4x4 m16n8k16 tiles. 3 split passes. Occupancy 2.
// SMEM row stride 72 bf16 (144B): conflict-free ldmatrix.
// ---------------------------------------------------------------------------
#define IG_AH   0
#define IG_AL   18432
#define IG_BH   36864
#define IG_BL   55296
#define IG_BIAS 73728
#define IG_SMEM 74240

__global__ __launch_bounds__(256, 2) void k_igemm(
    const float* __restrict__ x, const float* __restrict__ Wih,
    const float* __restrict__ bih, const float* __restrict__ bhh,
    const float* __restrict__ in_mask)
{
    extern __shared__ __align__(16) char smem[];
    const uint32_t sb = smem_u32(smem);
    const int tid = threadIdx.x;
    const int l   = tid & 31;
    const int w   = tid >> 5;
    const int wy  = w >> 2;         // 0..1 (m half)
    const int wx  = w & 3;          // 0..3 (n quarter)
    const int n0  = blockIdx.x * 128;
    const int m0  = blockIdx.y * 128;

    float* sBias = (float*)(smem + IG_BIAS);
    if (tid < 128) sBias[tid] = bih[n0 + tid] + bhh[n0 + tid];

    // ldmatrix lane-address components
    const int rA = ((l >> 3) & 1) * 8 + (l & 7);
    const int kA = (l >> 4) * 8;
    const int nB = ((l >> 4) & 1) * 8 + (l & 7);
    const int kB = ((l >> 3) & 1) * 8;
    const uint32_t aOff = (uint32_t)(((wy * 64 + rA) * 72 + kA) * 2);
    const uint32_t bOff = (uint32_t)(((wx * 32 + nB) * 72 + kB) * 2);

    float acc[4][4][4] = {};

    for (int ch = 0; ch < 8; ch++) {
        const int kk = ch * 64;
        __syncthreads();
        // Stage x tile: 128 rows x 64 k -> hi/lo
#pragma unroll
        for (int i = 0; i < 8; i++) {
            int v = tid + i * 256;
            int r = v >> 4;
            int kq = (v & 15) * 4;
            int m = m0 + r;
            float4 xv = *(const float4*)(x + (size_t)m * D_ + kk + kq);
            if ((m & (T_ - 1)) == 0) {
                const float* im = in_mask + (m >> 9) * D_ + kk + kq;
                xv.x *= im[0]; xv.y *= im[1]; xv.z *= im[2]; xv.w *= im[3];
            }
            uint32_t h0, l0, h1, l1;
            split2(xv.x, xv.y, h0, l0);
            split2(xv.z, xv.w, h1, l1);
            uint32_t off = (uint32_t)((r * 72 + kq) * 2);
            *(uint2*)(smem + IG_AH + off) = make_uint2(h0, h1);
            *(uint2*)(smem + IG_AL + off) = make_uint2(l0, l1);
        }
        // Stage Wih tile: 128 rows x 64 k -> hi/lo
#pragma unroll
        for (int i = 0; i < 8; i++) {
            int v = tid + i * 256;
            int r = v >> 4;
            int kq = (v & 15) * 4;
            float4 wv = *(const float4*)(Wih + (size_t)(n0 + r) * D_ + kk + kq);
            uint32_t h0, l0, h1, l1;
            split2(wv.x, wv.y, h0, l0);
            split2(wv.z, wv.w, h1, l1);
            uint32_t off = (uint32_t)((r * 72 + kq) * 2);
            *(uint2*)(smem + IG_BH + off) = make_uint2(h0, h1);
            *(uint2*)(smem + IG_BL + off) = make_uint2(l0, l1);
        }
        __syncthreads();

#pragma unroll
        for (int pass = 0; pass < 3; pass++) {
            uint32_t aBase = sb + ((pass == 1) ? IG_AL : IG_AH) + aOff;
            uint32_t bBase = sb + ((pass == 2) ? IG_BL : IG_BH) + bOff;
#pragma unroll
            for (int ks = 0; ks < 4; ks++) {
                uint32_t af[4][4];
#pragma unroll
                for (int mt = 0; mt < 4; mt++)
                    ldm4(aBase + mt * 2304 + ks * 32, af[mt]);
                uint32_t bf[4][2];
#pragma unroll
                for (int p = 0; p < 2; p++) {
                    uint32_t r4[4];
                    ldm4(bBase + p * 2304 + ks * 32, r4);
                    bf[p * 2][0] = r4[0]; bf[p * 2][1] = r4[1];
                    bf[p * 2 + 1][0] = r4[2]; bf[p * 2 + 1][1] = r4[3];
                }
#pragma unroll
                for (int mt = 0; mt < 4; mt++)
#pragma unroll
                    for (int nt = 0; nt < 4; nt++)
                        mma16816(acc[mt][nt], af[mt], bf[nt]);
            }
        }
    }

    // Epilogue: bias + store
#pragma unroll
    for (int mt = 0; mt < 4; mt++) {
        int mrow = m0 + wy * 64 + mt * 16 + (l >> 2);
#pragma unroll
        for (int nt = 0; nt < 4; nt++) {
            int nl = wx * 32 + nt * 8 + (l & 3) * 2;
            float b0 = sBias[nl], b1 = sBias[nl + 1];
            *(float2*)(g_xw + (size_t)mrow * G_ + n0 + nl) =
                make_float2(acc[mt][nt][0] + b0, acc[mt][nt][1] + b1);
            *(float2*)(g_xw + (size_t)(mrow + 8) * G_ + n0 + nl) =
                make_float2(acc[mt][nt][2] + b0, acc[mt][nt][3] + b1);
        }
    }
}

// ---------------------------------------------------------------------------
// Global grid barrier (CG grid.sync pattern: block bar + one-thread gpu fence)
// ---------------------------------------------------------------------------
__device__ __forceinline__ void gsync(unsigned int& tgt) {
    __syncthreads();
    if (threadIdx.x == 0) {
        asm volatile("fence.acq_rel.gpu;" ::: "memory");
        atomicAdd(&g_bar, 1u);
        tgt += NBLK;
        while (*(volatile unsigned int*)&g_bar < tgt) {}
        asm volatile("fence.acq_rel.gpu;" ::: "memory");
    }
    __syncthreads();
}
// Quartet barrier: only the 4 blocks sharing rt (split-k peers) sync.
__device__ __forceinline__ void qsync(int rt, unsigned int& tgt1) {
    __syncthreads();
    if (threadIdx.x == 0) {
        asm volatile("fence.acq_rel.gpu;" ::: "memory");
        atomicAdd(&g_bar1[rt * 32], 1u);
        tgt1 += KS_;
        while (*(volatile unsigned int*)&g_bar1[rt * 32] < tgt1) {}
        asm volatile("fence.acq_rel.gpu;" ::: "memory");
    }
    __syncthreads();
}

// ---------------------------------------------------------------------------
// Persistent recurrence (HMMA). Grid 128 blocks x 256 threads (8 warps).
// Block (rt = bid>>2, ks = bid&3): A = 128 gathered gate-rows, warp tile
// m32 x n32 (mq = w&3, nh = w>>2). W slice bf16 hi/lo SMEM ONCE (132 KB).
// R13 change (single): barrier #1 (partials->reduce) is now a QUARTET sync
// (only the 4 split-k peers of rt), not global. Safety: the global barrier #2
// still orders (a) all staging reads of h(t) before pointwise writes of
// h(t+1) -- h is parity double-buffered so even the (t+1)-write targets the
// other buffer -- and (b) all reduce reads of partials(t) before any
// partials(t+1) writes, so partials need no extra buffering.
// ---------------------------------------------------------------------------
#define PSS     264
#define PS_WH   0
#define PS_WL   67584
#define PS_HH   135168
#define PS_HL   168960
#define PS_SMEM 202752

__global__ __launch_bounds__(256, 1) void k_persist(
    const float* __restrict__ Whh,
    const float* __restrict__ hid_mask,
    const float* __restrict__ out_mask,
    float* __restrict__ out)
{
    extern __shared__ __align__(16) char smem[];
    const uint32_t sb = smem_u32(smem);
    const int tid = threadIdx.x;
    const int l   = tid & 31;
    const int w   = tid >> 5;
    const int mq  = w & 3;                 // 32-row group within 128
    const int nh  = w >> 2;                // 32-batch half
    const int bid = blockIdx.x;
    const int rt  = bid >> 2;
    const int ks  = bid & 3;
    const int kb  = ks * KB_;

    // ---- Convert + stage W slice once: 128 gathered rows x 256 k ----
#pragma unroll
    for (int i = 0; i < 32; i++) {
        int v  = tid + i * 256;            // 0..8191
        int lr = v >> 6;                   // 0..127
        int kq = (v & 63) * 4;             // 0..252
        int grow = (lr >> 5) * H_ + rt * 32 + (lr & 31);
        float4 wv = *(const float4*)(Whh + (size_t)grow * H_ + kb + kq);
        uint32_t h0, l0, h1, l1;
        split2(wv.x, wv.y, h0, l0);
        split2(wv.z, wv.w, h1, l1);
        uint32_t off = (uint32_t)((lr * PSS + kq) * 2);
        *(uint2*)(smem + PS_WH + off) = make_uint2(h0, h1);
        *(uint2*)(smem + PS_WL + off) = make_uint2(l0, l1);
    }
    __syncthreads();                       // W staged before first MMA

    // ---- Register-resident state: thread owns (b, j0) and (b, j0+1) ----
    const int bb = tid & 63;               // batch
    const int jp = tid >> 6;               // 0..3 -> j pair
    const int j0 = rt * 32 + ks * 8 + jp * 2;
    const int hidx0 = bb * H_ + j0;
    float c_reg[2] = {0.f, 0.f};
    float2 hmk = *(const float2*)(hid_mask + hidx0);
    float2 omk = *(const float2*)(out_mask + hidx0);

    // ldmatrix lane-address components
    const int rA = ((l >> 3) & 1) * 8 + (l & 7);
    const int kA = (l >> 4) * 8;
    const int nB = ((l >> 4) & 1) * 8 + (l & 7);
    const int kB = ((l >> 3) & 1) * 8;
    const uint32_t aOff = (uint32_t)(((mq * 32 + rA) * PSS + kA) * 2);
    const uint32_t bOff = (uint32_t)(((nh * 32 + nB) * PSS + kB) * 2);
    unsigned int tgt = 0, tgt1 = 0;

    for (int t = 0; t < T_; t++) {
        // ---- Stage h slice via cp.async: 64 b x 256 k from parity buffer ----
        // (sH WAR vs previous step's ldmatrix reads is ordered by the global
        //  gsync at the end of the previous step; at t=0 by the sync above.)
        const __nv_bfloat16* hsrc = g_hmh[t & 1];
        const __nv_bfloat16* lsrc = g_hml[t & 1];
#pragma unroll
        for (int i = 0; i < 8; i++) {
            int v  = tid + i * 256;        // 0..2047
            int b  = v >> 5;               // 0..63
            int kq = (v & 31) * 8;         // 0..248
            uint32_t off = (uint32_t)((b * PSS + kq) * 2);
            cp16(sb + PS_HH + off, hsrc + (size_t)b * H_ + kb + kq);
            cp16(sb + PS_HL + off, lsrc + (size_t)b * H_ + kb + kq);
        }
        asm volatile("cp.async.wait_all;" ::: "memory");
        __syncthreads();

        // ---- Warp GEMM: 32 rows x 32 batches, K=256, 3 passes ----
        float acc[2][4][4];
#pragma unroll
        for (int mt = 0; mt < 2; mt++)
#pragma unroll
            for (int nt = 0; nt < 4; nt++)
#pragma unroll
                for (int q = 0; q < 4; q++) acc[mt][nt][q] = 0.f;

#pragma unroll
        for (int pass = 0; pass < 3; pass++) {
            uint32_t aBase = sb + ((pass == 1) ? PS_WL : PS_WH) + aOff;
            uint32_t bBase = sb + ((pass == 2) ? PS_HL : PS_HH) + bOff;
#pragma unroll 4
            for (int kk = 0; kk < 16; kk++) {
                uint32_t af[2][4];
                ldm4(aBase + kk * 32, af[0]);
                ldm4(aBase + 8448 + kk * 32, af[1]);   // +16 rows
                uint32_t bf[4][2];
#pragma unroll
                for (int p = 0; p < 2; p++) {
                    uint32_t r4[4];
                    ldm4(bBase + p * 8448 + kk * 32, r4);  // +16 batches per p
                    bf[p * 2][0] = r4[0]; bf[p * 2][1] = r4[1];
                    bf[p * 2 + 1][0] = r4[2]; bf[p * 2 + 1][1] = r4[3];
                }
#pragma unroll
                for (int mt = 0; mt < 2; mt++)
#pragma unroll
                    for (int nt = 0; nt < 4; nt++)
                        mma16816(acc[mt][nt], af[mt], bf[nt]);
            }
        }

        // ---- Prefetch xw(t) (hides DRAM latency under stores+barrier) ----
        float xwv[2][4];
#pragma unroll
        for (int u = 0; u < 2; u++)
#pragma unroll
            for (int g = 0; g < 4; g++)
                xwv[u][g] = g_xw[(size_t)(bb * T_ + t) * G_ + g * H_ + j0 + u];

        // ---- Store partials: [ks][rowc][b] ----
#pragma unroll
        for (int mt = 0; mt < 2; mt++) {
            int row = rt * 128 + mq * 32 + mt * 16 + (l >> 2);
#pragma unroll
            for (int nt = 0; nt < 4; nt++) {
                int b = nh * 32 + nt * 8 + (l & 3) * 2;
                *(float2*)(&g_part[ks][row][b]) =
                    make_float2(acc[mt][nt][0], acc[mt][nt][1]);
                *(float2*)(&g_part[ks][row + 8][b]) =
                    make_float2(acc[mt][nt][2], acc[mt][nt][3]);
            }
        }

        qsync(rt, tgt1);   // only the 4 split-k peers of this rt

        // ---- Reduce + pointwise (2 adjacent j per thread) ----
        float cn[2], hn[2], hm[2];
#pragma unroll
        for (int u = 0; u < 2; u++) {
            float s[4];
#pragma unroll
            for (int g = 0; g < 4; g++) {
                int rowc = rt * 128 + g * 32 + ks * 8 + jp * 2 + u;
                float a = xwv[u][g];
                a += __ldcg(&g_part[0][rowc][bb]);
                a += __ldcg(&g_part[1][rowc][bb]);
                a += __ldcg(&g_part[2][rowc][bb]);
                a += __ldcg(&g_part[3][rowc][bb]);
                s[g] = a;
            }
            float i_ = sigf(s[0]);
            float f_ = sigf(s[1]);
            float gg = tanh_fast(s[2]);
            float o_ = sigf(s[3]);
            cn[u] = fmaf(f_, c_reg[u], i_ * gg);
            hn[u] = o_ * tanh_fast(cn[u]);
            hm[u] = hn[u] * ((u == 0) ? hmk.x : hmk.y);
            c_reg[u] = cn[u];
        }
        // Vectorized state + output stores (adjacent j) -> other parity buffer
        {
            __nv_bfloat16 h0 = __float2bfloat16(hm[0]);
            __nv_bfloat16 h1 = __float2bfloat16(hm[1]);
            __nv_bfloat16 l0 = __float2bfloat16(hm[0] - __bfloat162float(h0));
            __nv_bfloat16 l1 = __float2bfloat16(hm[1] - __bfloat162float(h1));
            *(__nv_bfloat162*)(&g_hmh[(t + 1) & 1][hidx0]) = __nv_bfloat162(h0, h1);
            *(__nv_bfloat162*)(&g_hml[(t + 1) & 1][hidx0]) = __nv_bfloat162(l0, l1);
            *(float2*)(out + (size_t)(bb * T_ + t) * H_ + j0) =
                make_float2(hn[0] * omk.x, hn[1] * omk.y);
            if (t == T_ - 1) {
                *(float2*)(out + (size_t)B_ * T_ * H_ + hidx0) =
                    make_float2(hm[0], hm[1]);                                 // h_f
                *(float2*)(out + (size_t)B_ * T_ * H_ + (size_t)B_ * H_ + hidx0) =
                    make_float2(cn[0], cn[1]);                                 // c_f
            }
        }

        if (t + 1 < T_) gsync(tgt);        // global: h(t+1) ready for all
    }
}

// ---------------------------------------------------------------------------
// Launch: 3 graph nodes (init, input GEMM, persistent recurrence)
// ---------------------------------------------------------------------------
extern "C" void kernel_launch(void* const* d_in, const int* in_sizes, int n_in,
                              void* d_out, int out_size)
{
    const float* x        = (const float*)d_in[0];
    const float* Wih      = (const float*)d_in[1];
    const float* Whh      = (const float*)d_in[2];
    const float* bih      = (const float*)d_in[3];
    const float* bhh      = (const float*)d_in[4];
    const float* in_mask  = (const float*)d_in[5];
    const float* hid_mask = (const float*)d_in[6];
    const float* out_mask = (const float*)d_in[7];
    float* out = (float*)d_out;

    static int attr_set = 0;
    if (!attr_set) {
        cudaFuncSetAttribute(k_igemm,   cudaFuncAttributeMaxDynamicSharedMemorySize, IG_SMEM);
        cudaFuncSetAttribute(k_persist, cudaFuncAttributeMaxDynamicSharedMemorySize, PS_SMEM);
        attr_set = 1;
    }

    k_init<<<256, 256>>>();
    k_igemm<<<dim3(G_ / 128, (B_ * T_) / 128), 256, IG_SMEM>>>(x, Wih, bih, bhh, in_mask);
    k_persist<<<NBLK, 256, PS_SMEM>>>(Whh, hid_mask, out_mask, out);
}